// round 11
// baseline (speedup 1.0000x reference)
#include <cuda_runtime.h>
#include <cstdint>

// C = triu(A @ B), A,B upper-triangular fp32, N=4096, sm_103 base target.
// mma.sync.m16n8k8 tf32, 3-product split:
//   hi = x & 0xFFFFE000, lo = tf32(x - hi);  C = Ahi*Bhi + Ahi*Blo + Alo*Bhi
//
// R10: split-K. Each tile's k-span [bi*128,(bj+1)*128) is cut into chunks of
// <= 8 k128-blocks (K=1024): 1000 work CTAs; longest chunk ~49us exclusive
// (was ~196us) -> critical path broken. C pre-zeroed by a first kernel;
// single-chunk tiles plain-store, multi-chunk tiles accumulate with
// red.global.add.f32. Mainloop unchanged from R9: 128 thr, 4 warps of 64x64,
// cp.async BK=32 3-stage, hi/lo split at fragment-load time.

#define NN 4096
#define BK 32
#define THREADS 128
#define N_CHUNKS 1000
#define CHUNK_BLOCKS 8               // k128-blocks per chunk

#define APITCH 36
#define BPITCH 136
#define A_FL (128 * APITCH)
#define B_FL (BK * BPITCH)
#define BUF_FL (A_FL + B_FL)
#define NBUF 3
#define SMEM_BYTES (NBUF * BUF_FL * 4)   // 107520

static __device__ __forceinline__ float tf32hi(float x) {
    return __uint_as_float(__float_as_uint(x) & 0xFFFFE000u);
}
static __device__ __forceinline__ uint32_t tf32lo(float x, float hi) {
    float r;
    asm("cvt.rna.tf32.f32 %0, %1;" : "=f"(r) : "f"(x - hi));
    return __float_as_uint(r);
}
static __device__ __forceinline__ void mma8(float* d, const uint32_t* a,
                                            const uint32_t* b) {
    asm volatile(
        "mma.sync.aligned.m16n8k8.row.col.f32.tf32.tf32.f32 "
        "{%0,%1,%2,%3}, {%4,%5,%6,%7}, {%8,%9}, {%0,%1,%2,%3};"
        : "+f"(d[0]), "+f"(d[1]), "+f"(d[2]), "+f"(d[3])
        : "r"(a[0]), "r"(a[1]), "r"(a[2]), "r"(a[3]), "r"(b[0]), "r"(b[1]));
}
static __device__ __forceinline__ void cp16(uint32_t dst, const void* src) {
    asm volatile("cp.async.cg.shared.global [%0], [%1], 16;"
                 :: "r"(dst), "l"(src));
}
static __device__ __forceinline__ void redadd(float* p, float v) {
    asm volatile("red.global.add.f32 [%0], %1;" :: "l"(p), "f"(v) : "memory");
}
static __device__ __forceinline__ uint32_t smem_u32(const void* p) {
    uint32_t a;
    asm("{ .reg .u64 t; cvta.to.shared.u64 t, %1; cvt.u32.u64 %0, t; }"
        : "=r"(a) : "l"(p));
    return a;
}

__global__ __launch_bounds__(256)
void zero_c(float* __restrict__ C) {
    const float4 z = make_float4(0.f, 0.f, 0.f, 0.f);
    size_t base = (size_t)blockIdx.x * 256 * 4 + threadIdx.x;
    float4* p = reinterpret_cast<float4*>(C);
    #pragma unroll
    for (int i = 0; i < 4; ++i)
        p[base + (size_t)i * 256] = z;
}

static __device__ __forceinline__ void issue_tile(
    const float* __restrict__ A, const float* __restrict__ B,
    uint32_t sdst, int rowBase, int colBase, int k0, int tid) {
    #pragma unroll
    for (int c = 0; c < 8; ++c) {
        int idx = c * 128 + tid;
        int row = idx >> 3, q = idx & 7;
        cp16(sdst + (uint32_t)(row * APITCH + q * 4) * 4u,
             A + (size_t)(rowBase + row) * NN + k0 + q * 4);
    }
    #pragma unroll
    for (int c = 0; c < 8; ++c) {
        int idx = c * 128 + tid;
        int kr = idx >> 5, q = idx & 31;
        cp16(sdst + (uint32_t)(A_FL + kr * BPITCH + q * 4) * 4u,
             B + (size_t)(k0 + kr) * NN + colBase + q * 4);
    }
}

__global__ __launch_bounds__(THREADS)
void triu_mm_mma(const float* __restrict__ A, const float* __restrict__ B,
                 float* __restrict__ C) {
    const int tid = threadIdx.x;

    // Map chunk id -> (bi, bj, chunk index). Longest diagonals first.
    int bi = 0, bj = 0, ci = 0, cpt = 1;
    {
        int rem = blockIdx.x;
        #pragma unroll 1
        for (int d = 31; d >= 0; --d) {
            int c = (d + 8) / 8;               // chunks per tile, ceil((d+1)/8)
            int cnt = (32 - d) * c;
            if (rem < cnt) { cpt = c; bi = rem / c; ci = rem % c; bj = bi + d; break; }
            rem -= cnt;
        }
    }
    const int rowBase = bi * 128, colBase = bj * 128;
    const int spanEnd = colBase + 128;                       // tile k-end
    const int kStart = rowBase + ci * (CHUNK_BLOCKS * 128);
    const int kEnd = min(kStart + CHUNK_BLOCKS * 128, spanEnd);
    const int nSteps = (kEnd - kStart) / BK;                 // >= 4

    extern __shared__ float smem[];
    const uint32_t sbase = smem_u32(smem);

    const int lane = tid & 31, wid = tid >> 5;
    const int wm = (wid & 1) * 64;
    const int wn = (wid >> 1) * 64;
    const int g = lane >> 2, tq = lane & 3;

    float acc[4][8][4];
    #pragma unroll
    for (int mt = 0; mt < 4; ++mt)
        #pragma unroll
        for (int nt = 0; nt < 8; ++nt)
            #pragma unroll
            for (int i = 0; i < 4; ++i) acc[mt][nt][i] = 0.f;

    issue_tile(A, B, sbase, rowBase, colBase, kStart, tid);
    asm volatile("cp.async.commit_group;" ::: "memory");
    issue_tile(A, B, sbase + BUF_FL * 4u, rowBase, colBase, kStart + BK, tid);
    asm volatile("cp.async.commit_group;" ::: "memory");

    #pragma unroll 1
    for (int i = 0; i < nSteps; ++i) {
        asm volatile("cp.async.wait_group 1;" ::: "memory");
        __syncthreads();

        if (i + 2 < nSteps) {
            issue_tile(A, B, sbase + (uint32_t)((i + 2) % 3) * (BUF_FL * 4u),
                       rowBase, colBase, kStart + (i + 2) * BK, tid);
        }
        asm volatile("cp.async.commit_group;" ::: "memory");

        const float* buf = smem + (i % 3) * BUF_FL;
        #pragma unroll
        for (int s = 0; s < 4; ++s) {
            const int kk = s * 8 + tq;

            uint32_t bh[8][2], bl[8][2];
            #pragma unroll
            for (int nt = 0; nt < 8; ++nt) {
                const int c0 = wn + nt * 8 + g;
                float r0 = buf[A_FL + kk * BPITCH + c0];
                float r1 = buf[A_FL + (kk + 4) * BPITCH + c0];
                float h0 = tf32hi(r0), h1 = tf32hi(r1);
                bh[nt][0] = __float_as_uint(h0);
                bh[nt][1] = __float_as_uint(h1);
                bl[nt][0] = tf32lo(r0, h0);
                bl[nt][1] = tf32lo(r1, h1);
            }
            #pragma unroll
            for (int mt = 0; mt < 4; ++mt) {
                const int r0 = wm + mt * 16 + g;
                float a0 = buf[r0 * APITCH + kk];
                float a1 = buf[(r0 + 8) * APITCH + kk];
                float a2 = buf[r0 * APITCH + kk + 4];
                float a3 = buf[(r0 + 8) * APITCH + kk + 4];
                float h0 = tf32hi(a0), h1 = tf32hi(a1);
                float h2 = tf32hi(a2), h3 = tf32hi(a3);
                uint32_t ah[4] = {__float_as_uint(h0), __float_as_uint(h1),
                                  __float_as_uint(h2), __float_as_uint(h3)};
                uint32_t al[4] = {tf32lo(a0, h0), tf32lo(a1, h1),
                                  tf32lo(a2, h2), tf32lo(a3, h3)};
                #pragma unroll
                for (int nt = 0; nt < 8; ++nt)
                    mma8(acc[mt][nt], ah, bh[nt]);
                #pragma unroll
                for (int nt = 0; nt < 8; ++nt)
                    mma8(acc[mt][nt], ah, bl[nt]);
                #pragma unroll
                for (int nt = 0; nt < 8; ++nt)
                    mma8(acc[mt][nt], al, bh[nt]);
            }
        }
    }

    // Epilogue. Single-chunk tiles: sole writer, plain stores over zeros.
    // Multi-chunk tiles: accumulate with no-return global f32 adds.
    if (cpt == 1) {
        #pragma unroll
        for (int mt = 0; mt < 4; ++mt) {
            #pragma unroll
            for (int nt = 0; nt < 8; ++nt) {
                const int r0 = rowBase + wm + mt * 16 + g;
                const int c0 = colBase + wn + nt * 8 + tq * 2;
                float2 v01 = make_float2(acc[mt][nt][0], acc[mt][nt][1]);
                float2 v23 = make_float2(acc[mt][nt][2], acc[mt][nt][3]);
                *reinterpret_cast<float2*>(C + (size_t)r0 * NN + c0) = v01;
                *reinterpret_cast<float2*>(C + (size_t)(r0 + 8) * NN + c0) = v23;
            }
        }
    } else {
        #pragma unroll
        for (int mt = 0; mt < 4; ++mt) {
            #pragma unroll
            for (int nt = 0; nt < 8; ++nt) {
                const int r0 = rowBase + wm + mt * 16 + g;
                const int c0 = colBase + wn + nt * 8 + tq * 2;
                float* p0 = C + (size_t)r0 * NN + c0;
                float* p1 = C + (size_t)(r0 + 8) * NN + c0;
                redadd(p0, acc[mt][nt][0]);
                redadd(p0 + 1, acc[mt][nt][1]);
                redadd(p1, acc[mt][nt][2]);
                redadd(p1 + 1, acc[mt][nt][3]);
            }
        }
    }
}

extern "C" void kernel_launch(void* const* d_in, const int* in_sizes, int n_in,
                              void* d_out, int out_size) {
    const float* A = (const float*)d_in[0];
    const float* B = (const float*)d_in[1];
    float* C = (float*)d_out;

    // Pass 1: zero C (4096^2 floats = 4.19M float4; 4096 blocks x 256 thr x 4).
    zero_c<<<4096, 256>>>(C);

    // Pass 2: split-K triangular matmul.
    cudaFuncSetAttribute(triu_mm_mma,
                         cudaFuncAttributeMaxDynamicSharedMemorySize, SMEM_BYTES);
    triu_mm_mma<<<N_CHUNKS, THREADS, SMEM_BYTES>>>(A, B, C);
}

// round 13
// speedup vs baseline: 2.2826x; 2.2826x over previous
#include <cuda_runtime.h>
#include <cstdint>

// C = triu(A @ B), A,B upper-triangular fp32, N=4096, sm_103 base target.
// R11: bf16 mma.sync.m16n8k16 (K=16/instr -> half the mma count of tf32 k8)
// with 3-term split for accuracy:
//   hi = bf16(x), lo = bf16(x - hi);  C = Ahi*Bhi + Ahi*Blo + Alo*Bhi
//   (dropped lo*lo and lo-rounding are O(2^-16) per product -> rel ~5e-5)
//
// 128-thread CTA, 4 warps of 64x64 (acc=128 regs). Raw fp32 staged in smem
// via cp.async (BK=32, 3-stage, one __syncthreads per step); bf16 hi/lo
// split at fragment-load time via cvt.rn.bf16x2.f32. Conflict-free pitches
// re-derived for paired access: A:40 (banks 8g+2tq), B:132 (banks 8tq+g).
// Triangular k-range per tile [bi*128,(bj+1)*128); longest tiles first;
// strictly-lower blocks zero-filled by tail CTAs. No split-K (R10 regressed).

#define NN 4096
#define BK 32
#define THREADS 128
#define N_WORK 528
#define N_ZERO 496

#define APITCH 40                    // 32 + 8 pad
#define BPITCH 132                   // 128 + 4 pad
#define A_FL (128 * APITCH)          // 5120 floats
#define B_FL (BK * BPITCH)           // 4224 floats
#define BUF_FL (A_FL + B_FL)         // 9344 floats
#define NBUF 3
#define SMEM_BYTES (NBUF * BUF_FL * 4)   // 112128 (x2 CTAs = 224.3KB <= 228KB)

// Pack two floats (k, k+1) into one bf16x2 reg: lo half = f0, hi half = f1.
static __device__ __forceinline__ uint32_t pack_bf16x2(float f0, float f1) {
    uint32_t r;
    asm("cvt.rn.bf16x2.f32 %0, %1, %2;" : "=r"(r) : "f"(f1), "f"(f0));
    return r;
}
// Split a k-pair of floats into bf16 hi and lo packed regs.
static __device__ __forceinline__ void split2(float f0, float f1,
                                              uint32_t& h, uint32_t& l) {
    h = pack_bf16x2(f0, f1);
    float h0 = __uint_as_float(h << 16);
    float h1 = __uint_as_float(h & 0xFFFF0000u);
    l = pack_bf16x2(f0 - h0, f1 - h1);
}
static __device__ __forceinline__ void mma16(float* d, const uint32_t* a,
                                             const uint32_t* b) {
    asm volatile(
        "mma.sync.aligned.m16n8k16.row.col.f32.bf16.bf16.f32 "
        "{%0,%1,%2,%3}, {%4,%5,%6,%7}, {%8,%9}, {%0,%1,%2,%3};"
        : "+f"(d[0]), "+f"(d[1]), "+f"(d[2]), "+f"(d[3])
        : "r"(a[0]), "r"(a[1]), "r"(a[2]), "r"(a[3]), "r"(b[0]), "r"(b[1]));
}
static __device__ __forceinline__ void cp16(uint32_t dst, const void* src) {
    asm volatile("cp.async.cg.shared.global [%0], [%1], 16;"
                 :: "r"(dst), "l"(src));
}
static __device__ __forceinline__ uint32_t smem_u32(const void* p) {
    uint32_t a;
    asm("{ .reg .u64 t; cvta.to.shared.u64 t, %1; cvt.u32.u64 %0, t; }"
        : "=r"(a) : "l"(p));
    return a;
}

// cp.async one BK=32 tile (A 128x32, B 32x128) into buffer.
static __device__ __forceinline__ void issue_tile(
    const float* __restrict__ A, const float* __restrict__ B,
    uint32_t sdst, int rowBase, int colBase, int k0, int tid) {
    #pragma unroll
    for (int c = 0; c < 8; ++c) {
        int idx = c * 128 + tid;
        int row = idx >> 3, q = idx & 7;
        cp16(sdst + (uint32_t)(row * APITCH + q * 4) * 4u,
             A + (size_t)(rowBase + row) * NN + k0 + q * 4);
    }
    #pragma unroll
    for (int c = 0; c < 8; ++c) {
        int idx = c * 128 + tid;
        int kr = idx >> 5, q = idx & 31;
        cp16(sdst + (uint32_t)(A_FL + kr * BPITCH + q * 4) * 4u,
             B + (size_t)(k0 + kr) * NN + colBase + q * 4);
    }
}

__global__ __launch_bounds__(THREADS)
void triu_mm_bf16(const float* __restrict__ A, const float* __restrict__ B,
                  float* __restrict__ C) {
    const int t = blockIdx.x;
    const int tid = threadIdx.x;

    if (t >= N_WORK) {
        // Strictly-lower 128x128 block: exactly zero.
        int rem = t - N_WORK, bi = 0, bj = 0;
        #pragma unroll 1
        for (int db = 1; db < 32; ++db) {
            int c = 32 - db;
            if (rem < c) { bj = rem; bi = rem + db; break; }
            rem -= c;
        }
        const float4 z = make_float4(0.f, 0.f, 0.f, 0.f);
        const int rowBase = bi * 128, colBase = bj * 128;
        #pragma unroll
        for (int it = 0; it < 32; ++it) {
            int idx = it * 128 + tid;
            int r = idx >> 5, c4 = idx & 31;
            *reinterpret_cast<float4*>(
                C + (size_t)(rowBase + r) * NN + colBase + c4 * 4) = z;
        }
        return;
    }

    int bi = 0, bj = 0;
    {
        int rem = t;
        #pragma unroll 1
        for (int d = 31; d >= 0; --d) {
            int c = 32 - d;
            if (rem < c) { bi = rem; bj = rem + d; break; }
            rem -= c;
        }
    }
    const int rowBase = bi * 128, colBase = bj * 128;
    const int kStart = rowBase, kEnd = colBase + 128;
    const int nSteps = (kEnd - kStart) / BK;   // >= 4

    extern __shared__ float smem[];
    const uint32_t sbase = smem_u32(smem);

    const int lane = tid & 31, wid = tid >> 5;
    const int wm = (wid & 1) * 64;
    const int wn = (wid >> 1) * 64;
    const int g = lane >> 2, tq = lane & 3;

    float acc[4][8][4];
    #pragma unroll
    for (int mt = 0; mt < 4; ++mt)
        #pragma unroll
        for (int nt = 0; nt < 8; ++nt)
            #pragma unroll
            for (int i = 0; i < 4; ++i) acc[mt][nt][i] = 0.f;

    issue_tile(A, B, sbase, rowBase, colBase, kStart, tid);
    asm volatile("cp.async.commit_group;" ::: "memory");
    issue_tile(A, B, sbase + BUF_FL * 4u, rowBase, colBase, kStart + BK, tid);
    asm volatile("cp.async.commit_group;" ::: "memory");

    #pragma unroll 1
    for (int i = 0; i < nSteps; ++i) {
        asm volatile("cp.async.wait_group 1;" ::: "memory");
        __syncthreads();

        if (i + 2 < nSteps) {
            issue_tile(A, B, sbase + (uint32_t)((i + 2) % 3) * (BUF_FL * 4u),
                       rowBase, colBase, kStart + (i + 2) * BK, tid);
        }
        asm volatile("cp.async.commit_group;" ::: "memory");

        const float* buf = smem + (i % 3) * BUF_FL;
        #pragma unroll
        for (int s = 0; s < 2; ++s) {           // two k16 substeps per BK=32
            const int kk = s * 16;
            const int kb = kk + 2 * tq;

            // B fragments: raw fp32 -> bf16 hi/lo pairs at load time.
            uint32_t bh[8][2], bl[8][2];
            #pragma unroll
            for (int nt = 0; nt < 8; ++nt) {
                const int c0 = wn + nt * 8 + g;
                split2(buf[A_FL + kb * BPITCH + c0],
                       buf[A_FL + (kb + 1) * BPITCH + c0],
                       bh[nt][0], bl[nt][0]);
                split2(buf[A_FL + (kb + 8) * BPITCH + c0],
                       buf[A_FL + (kb + 9) * BPITCH + c0],
                       bh[nt][1], bl[nt][1]);
            }
            // A per mt: float2 pair loads, convert, 3 passes over nt.
            #pragma unroll
            for (int mt = 0; mt < 4; ++mt) {
                const int r0 = wm + mt * 16 + g;
                float2 f01 = *reinterpret_cast<const float2*>(
                    &buf[r0 * APITCH + kb]);
                float2 f23 = *reinterpret_cast<const float2*>(
                    &buf[(r0 + 8) * APITCH + kb]);
                float2 f45 = *reinterpret_cast<const float2*>(
                    &buf[r0 * APITCH + kb + 8]);
                float2 f67 = *reinterpret_cast<const float2*>(
                    &buf[(r0 + 8) * APITCH + kb + 8]);
                uint32_t ah[4], al[4];
                split2(f01.x, f01.y, ah[0], al[0]);
                split2(f23.x, f23.y, ah[1], al[1]);
                split2(f45.x, f45.y, ah[2], al[2]);
                split2(f67.x, f67.y, ah[3], al[3]);
                #pragma unroll
                for (int nt = 0; nt < 8; ++nt)
                    mma16(acc[mt][nt], ah, bh[nt]);
                #pragma unroll
                for (int nt = 0; nt < 8; ++nt)
                    mma16(acc[mt][nt], ah, bl[nt]);
                #pragma unroll
                for (int nt = 0; nt < 8; ++nt)
                    mma16(acc[mt][nt], al, bh[nt]);
            }
        }
    }

    // Epilogue: fragment layout direct to global (float2, sector-coalesced).
    #pragma unroll
    for (int mt = 0; mt < 4; ++mt) {
        #pragma unroll
        for (int nt = 0; nt < 8; ++nt) {
            const int r0 = rowBase + wm + mt * 16 + g;
            const int c0 = colBase + wn + nt * 8 + tq * 2;
            float2 v01 = make_float2(acc[mt][nt][0], acc[mt][nt][1]);
            float2 v23 = make_float2(acc[mt][nt][2], acc[mt][nt][3]);
            *reinterpret_cast<float2*>(C + (size_t)r0 * NN + c0) = v01;
            *reinterpret_cast<float2*>(C + (size_t)(r0 + 8) * NN + c0) = v23;
        }
    }
}

extern "C" void kernel_launch(void* const* d_in, const int* in_sizes, int n_in,
                              void* d_out, int out_size) {
    const float* A = (const float*)d_in[0];
    const float* B = (const float*)d_in[1];
    float* C = (float*)d_out;

    cudaFuncSetAttribute(triu_mm_bf16,
                         cudaFuncAttributeMaxDynamicSharedMemorySize, SMEM_BYTES);
    triu_mm_bf16<<<N_WORK + N_ZERO, THREADS, SMEM_BYTES>>>(A, B, C);
}

// round 14
// speedup vs baseline: 2.4185x; 1.0595x over previous
#include <cuda_runtime.h>
#include <cstdint>

// C = triu(A @ B), A,B upper-triangular fp32, N=4096, sm_103 base target.
// bf16 mma.sync.m16n8k16, 3-term split:
//   hi = bf16(x), lo = bf16(x - hi);  C = Ahi*Bhi + Ahi*Blo + Alo*Bhi
//
// R12: conversion moved to STAGING (bf16 hi/lo stored in smem — same bytes
// as raw fp32). Inner loop is pure LDS.32 + mma: no cvt chains on the
// fragment critical path (R11's stall source). 512-thread CTA, 16 warps of
// 32x32 (acc=32 regs; ~105 live regs, no cap needed), BK=32, double buffer,
// register-prefetch staging, one __syncthreads per step. Conflict-free u32
// pitches: A:20 (banks 20g+tq), B:136 (banks 8tq+g). Triangular k-range per
// tile; longest tiles first; strictly-lower blocks zero-filled by tail CTAs.

#define NN 4096
#define BK 32
#define THREADS 512
#define N_WORK 528
#define N_ZERO 496

// u32 units. A: [row][pair] 128x16 (+4 pad); B: [pair][n] 16x128 (+8 pad).
#define AP 20
#define BP 136
#define A_U (128 * AP)               // 2560 u32
#define B_U (16 * BP)                // 2176 u32
#define OAH 0
#define OAL A_U
#define OBH (2 * A_U)
#define OBL (2 * A_U + B_U)
#define BUF_U (2 * A_U + 2 * B_U)    // 9472 u32
#define SMEM_BYTES (2 * BUF_U * 4)   // 75776

// Pack floats (f0 -> low half, f1 -> high half) as bf16x2.
static __device__ __forceinline__ uint32_t pack_bf16x2(float f0, float f1) {
    uint32_t r;
    asm("cvt.rn.bf16x2.f32 %0, %1, %2;" : "=r"(r) : "f"(f1), "f"(f0));
    return r;
}
static __device__ __forceinline__ void split2(float f0, float f1,
                                              uint32_t& h, uint32_t& l) {
    h = pack_bf16x2(f0, f1);
    float h0 = __uint_as_float(h << 16);
    float h1 = __uint_as_float(h & 0xFFFF0000u);
    l = pack_bf16x2(f0 - h0, f1 - h1);
}
static __device__ __forceinline__ void mma16(float* d, const uint32_t* a,
                                             const uint32_t* b) {
    asm volatile(
        "mma.sync.aligned.m16n8k16.row.col.f32.bf16.bf16.f32 "
        "{%0,%1,%2,%3}, {%4,%5,%6,%7}, {%8,%9}, {%0,%1,%2,%3};"
        : "+f"(d[0]), "+f"(d[1]), "+f"(d[2]), "+f"(d[3])
        : "r"(a[0]), "r"(a[1]), "r"(a[2]), "r"(a[3]), "r"(b[0]), "r"(b[1]));
}

__global__ __launch_bounds__(THREADS, 1)
void triu_mm_bf16(const float* __restrict__ A, const float* __restrict__ B,
                  float* __restrict__ C) {
    const int t = blockIdx.x;
    const int tid = threadIdx.x;

    if (t >= N_WORK) {
        // Strictly-lower 128x128 block: exactly zero.
        int rem = t - N_WORK, bi = 0, bj = 0;
        #pragma unroll 1
        for (int db = 1; db < 32; ++db) {
            int c = 32 - db;
            if (rem < c) { bj = rem; bi = rem + db; break; }
            rem -= c;
        }
        const float4 z = make_float4(0.f, 0.f, 0.f, 0.f);
        const int rowBase = bi * 128, colBase = bj * 128;
        #pragma unroll
        for (int it = 0; it < 8; ++it) {
            int idx = it * 512 + tid;
            int r = idx >> 5, c4 = idx & 31;
            *reinterpret_cast<float4*>(
                C + (size_t)(rowBase + r) * NN + colBase + c4 * 4) = z;
        }
        return;
    }

    int bi = 0, bj = 0;
    {
        int rem = t;
        #pragma unroll 1
        for (int d = 31; d >= 0; --d) {
            int c = 32 - d;
            if (rem < c) { bi = rem; bj = rem + d; break; }
            rem -= c;
        }
    }
    const int rowBase = bi * 128, colBase = bj * 128;
    const int kStart = rowBase, kEnd = colBase + 128;
    const int nSteps = (kEnd - kStart) / BK;   // >= 4

    extern __shared__ uint32_t smem[];

    const int lane = tid & 31, wid = tid >> 5;
    const int wm = (wid & 3) * 32;        // 4 warps down
    const int wn = (wid >> 2) * 32;       // 4 warps across
    const int g = lane >> 2, tq = lane & 3;

    // Staging maps.
    // A: row = tid>>2 (128 rows), quad q = tid&3 -> pairs 4q..4q+3 (2 float4).
    const int ar = tid >> 2, aq = tid & 3;
    // B: pair-row p = tid>>5 (16), n-quad c = tid&31 -> pairs (p, 4c..4c+3).
    const int bp = tid >> 5, bc = tid & 31;

    float acc[2][4][4];
    #pragma unroll
    for (int mt = 0; mt < 2; ++mt)
        #pragma unroll
        for (int nt = 0; nt < 4; ++nt)
            #pragma unroll
            for (int i = 0; i < 4; ++i) acc[mt][nt][i] = 0.f;

    float4 pa0, pa1, pb0, pb1;
    {
        const float* ab = A + (size_t)(rowBase + ar) * NN + kStart + aq * 8;
        pa0 = *reinterpret_cast<const float4*>(ab);
        pa1 = *reinterpret_cast<const float4*>(ab + 4);
        const float* bb = B + (size_t)(kStart + 2 * bp) * NN + colBase + bc * 4;
        pb0 = *reinterpret_cast<const float4*>(bb);
        pb1 = *reinterpret_cast<const float4*>(bb + NN);
    }

    int curBuf = 0;

    // Stage tile 0: split to bf16 hi/lo in smem.
    {
        uint32_t* buf = smem;
        uint32_t h[4], l[4];
        // A: pairs are (k even, k odd) within the thread's 8 consecutive k.
        split2(pa0.x, pa0.y, h[0], l[0]);
        split2(pa0.z, pa0.w, h[1], l[1]);
        split2(pa1.x, pa1.y, h[2], l[2]);
        split2(pa1.z, pa1.w, h[3], l[3]);
        *reinterpret_cast<uint4*>(buf + OAH + ar * AP + aq * 4) =
            make_uint4(h[0], h[1], h[2], h[3]);
        *reinterpret_cast<uint4*>(buf + OAL + ar * AP + aq * 4) =
            make_uint4(l[0], l[1], l[2], l[3]);
        // B: pair = (row 2p, row 2p+1) at same column.
        split2(pb0.x, pb1.x, h[0], l[0]);
        split2(pb0.y, pb1.y, h[1], l[1]);
        split2(pb0.z, pb1.z, h[2], l[2]);
        split2(pb0.w, pb1.w, h[3], l[3]);
        *reinterpret_cast<uint4*>(buf + OBH + bp * BP + bc * 4) =
            make_uint4(h[0], h[1], h[2], h[3]);
        *reinterpret_cast<uint4*>(buf + OBL + bp * BP + bc * 4) =
            make_uint4(l[0], l[1], l[2], l[3]);
    }
    __syncthreads();

    #pragma unroll 1
    for (int step = 0; step < nSteps; ++step) {
        const bool hasNext = (step + 1) < nSteps;

        if (hasNext) {
            const int kN = kStart + (step + 1) * BK;
            const float* ab = A + (size_t)(rowBase + ar) * NN + kN + aq * 8;
            pa0 = *reinterpret_cast<const float4*>(ab);
            pa1 = *reinterpret_cast<const float4*>(ab + 4);
            const float* bb = B + (size_t)(kN + 2 * bp) * NN + colBase + bc * 4;
            pb0 = *reinterpret_cast<const float4*>(bb);
            pb1 = *reinterpret_cast<const float4*>(bb + NN);
        }

        const uint32_t* buf = smem + curBuf * BUF_U;
        #pragma unroll
        for (int s = 0; s < 2; ++s) {
            const int ps = s * 8;

            // Pure LDS fragment loads — no conversion.
            uint32_t ah[2][4], al[2][4], bh[4][2], bl[4][2];
            #pragma unroll
            for (int mt = 0; mt < 2; ++mt) {
                const int r0 = wm + mt * 16 + g;
                ah[mt][0] = buf[OAH + r0 * AP + ps + tq];
                ah[mt][1] = buf[OAH + (r0 + 8) * AP + ps + tq];
                ah[mt][2] = buf[OAH + r0 * AP + ps + tq + 4];
                ah[mt][3] = buf[OAH + (r0 + 8) * AP + ps + tq + 4];
                al[mt][0] = buf[OAL + r0 * AP + ps + tq];
                al[mt][1] = buf[OAL + (r0 + 8) * AP + ps + tq];
                al[mt][2] = buf[OAL + r0 * AP + ps + tq + 4];
                al[mt][3] = buf[OAL + (r0 + 8) * AP + ps + tq + 4];
            }
            #pragma unroll
            for (int nt = 0; nt < 4; ++nt) {
                const int c0 = wn + nt * 8 + g;
                bh[nt][0] = buf[OBH + (ps + tq) * BP + c0];
                bh[nt][1] = buf[OBH + (ps + tq + 4) * BP + c0];
                bl[nt][0] = buf[OBL + (ps + tq) * BP + c0];
                bl[nt][1] = buf[OBL + (ps + tq + 4) * BP + c0];
            }

            #pragma unroll
            for (int mt = 0; mt < 2; ++mt)
                #pragma unroll
                for (int nt = 0; nt < 4; ++nt)
                    mma16(acc[mt][nt], ah[mt], bh[nt]);
            #pragma unroll
            for (int mt = 0; mt < 2; ++mt)
                #pragma unroll
                for (int nt = 0; nt < 4; ++nt)
                    mma16(acc[mt][nt], ah[mt], bl[nt]);
            #pragma unroll
            for (int mt = 0; mt < 2; ++mt)
                #pragma unroll
                for (int nt = 0; nt < 4; ++nt)
                    mma16(acc[mt][nt], al[mt], bh[nt]);
        }

        if (hasNext) {
            uint32_t* nb = smem + (curBuf ^ 1) * BUF_U;
            uint32_t h[4], l[4];
            split2(pa0.x, pa0.y, h[0], l[0]);
            split2(pa0.z, pa0.w, h[1], l[1]);
            split2(pa1.x, pa1.y, h[2], l[2]);
            split2(pa1.z, pa1.w, h[3], l[3]);
            *reinterpret_cast<uint4*>(nb + OAH + ar * AP + aq * 4) =
                make_uint4(h[0], h[1], h[2], h[3]);
            *reinterpret_cast<uint4*>(nb + OAL + ar * AP + aq * 4) =
                make_uint4(l[0], l[1], l[2], l[3]);
            split2(pb0.x, pb1.x, h[0], l[0]);
            split2(pb0.y, pb1.y, h[1], l[1]);
            split2(pb0.z, pb1.z, h[2], l[2]);
            split2(pb0.w, pb1.w, h[3], l[3]);
            *reinterpret_cast<uint4*>(nb + OBH + bp * BP + bc * 4) =
                make_uint4(h[0], h[1], h[2], h[3]);
            *reinterpret_cast<uint4*>(nb + OBL + bp * BP + bc * 4) =
                make_uint4(l[0], l[1], l[2], l[3]);
            curBuf ^= 1;
        }
        __syncthreads();
    }

    // Epilogue: fragment layout direct to global (float2, sector-coalesced).
    #pragma unroll
    for (int mt = 0; mt < 2; ++mt) {
        #pragma unroll
        for (int nt = 0; nt < 4; ++nt) {
            const int r0 = rowBase + wm + mt * 16 + g;
            const int c0 = colBase + wn + nt * 8 + tq * 2;
            float2 v01 = make_float2(acc[mt][nt][0], acc[mt][nt][1]);
            float2 v23 = make_float2(acc[mt][nt][2], acc[mt][nt][3]);
            *reinterpret_cast<float2*>(C + (size_t)r0 * NN + c0) = v01;
            *reinterpret_cast<float2*>(C + (size_t)(r0 + 8) * NN + c0) = v23;
        }
    }
}

extern "C" void kernel_launch(void* const* d_in, const int* in_sizes, int n_in,
                              void* d_out, int out_size) {
    const float* A = (const float*)d_in[0];
    const float* B = (const float*)d_in[1];
    float* C = (float*)d_out;

    cudaFuncSetAttribute(triu_mm_bf16,
                         cudaFuncAttributeMaxDynamicSharedMemorySize, SMEM_BYTES);
    triu_mm_bf16<<<N_WORK + N_ZERO, THREADS, SMEM_BYTES>>>(A, B, C);
}